// round 14
// baseline (speedup 1.0000x reference)
#include <cuda_runtime.h>
#include <cuda_bf16.h>
#include <cstdint>

#define Bn 64
#define Ln 256
#define Vn 256
#define En 256
#define Hn 1024
#define NG3 3072
#define NBLK 128           // persistent blocks; each owns 8 hidden units
#define NJb 8
#define HB (Hn*Bn)
#define SLAB 262144        // h slab: [ver2][mt4][ks64][lane32][16B]
#define VERB 131072
#define BFRAG 24576        // u32 GRU B-fragment words per block (hi+lo)
#define SM_B 98304         // B fragments in smem (bytes)
#define SMEM_DYN SM_B

typedef unsigned int u32;
typedef unsigned long long u64;

__device__ float g_EW[Vn*NG3];                         // emb@Wi (+bh for r,z)
__device__ float g_HP[(size_t)(Ln+1)*HB];              // exact fp32 h, [t][b][j]
__device__ unsigned char g_YA[(size_t)(Ln+1)*SLAB];    // bf16 hi/lo fragment-order h
__device__ u32 g_WF[(size_t)NBLK*BFRAG];               // GRU B fragments per block
__device__ u32 g_WOF[64*32*32*4];                      // Wout B fragments (1MB)
__device__ u32 g_cnt[4*16*32];                         // (mt, ks-granule) release counters

__device__ __forceinline__ u32 smem_u32(const void* p) {
    u32 a;
    asm("{ .reg .u64 t; cvta.to.shared.u64 t, %1; cvt.u32.u64 %0, t; }" : "=r"(a) : "l"(p));
    return a;
}
__device__ __forceinline__ void cp16(u32 dst, const void* src) {
    asm volatile("cp.async.cg.shared.global [%0], [%1], 16;" :: "r"(dst), "l"(src) : "memory");
}
__device__ __forceinline__ void cp_commit() {
    asm volatile("cp.async.commit_group;" ::: "memory");
}
template<int N> __device__ __forceinline__ void cp_wait() {
    asm volatile("cp.async.wait_group %0;" :: "n"(N) : "memory");
}
__device__ __forceinline__ void mma_bf16(float* c, const u32* a, u32 b0, u32 b1) {
    asm volatile("mma.sync.aligned.m16n8k16.row.col.f32.bf16.bf16.f32 "
        "{%0,%1,%2,%3}, {%4,%5,%6,%7}, {%8,%9}, {%0,%1,%2,%3};"
        : "+f"(c[0]), "+f"(c[1]), "+f"(c[2]), "+f"(c[3])
        : "r"(a[0]), "r"(a[1]), "r"(a[2]), "r"(a[3]), "r"(b0), "r"(b1));
}
__device__ __forceinline__ unsigned short bf16r(float x) {
    return __bfloat16_as_ushort(__float2bfloat16_rn(x));
}
__device__ __forceinline__ u32 ld_acq(const u32* p) {
    u32 v;
    asm volatile("ld.acquire.gpu.global.u32 %0, [%1];" : "=r"(v) : "l"(p) : "memory");
    return v;
}
__device__ __forceinline__ void red_rel(u32* p) {
    asm volatile("red.release.gpu.global.add.u32 [%0], %1;" :: "l"(p), "r"(1u) : "memory");
}

// =================== reset ===================
__global__ void reset_kernel() {
    int tid = blockIdx.x * blockDim.x + threadIdx.x;
    int nt = gridDim.x * blockDim.x;
    for (int i = tid; i < HB; i += nt) g_HP[i] = 0.0f;
    for (int i = tid; i < SLAB / 4; i += nt) ((u32*)g_YA)[i] = 0u;
    if (tid < 4 * 16 * 32) g_cnt[tid] = 0u;
}

// =================== EW = embedding @ Wi (+ bh folded for r,z) ===================
__global__ __launch_bounds__(256) void ew_kernel(const float* __restrict__ emb,
                                                 const float* __restrict__ Wi,
                                                 const float* __restrict__ bh) {
    __shared__ float semb[32][En];
    int vbase = blockIdx.y * 32, cbase = blockIdx.x * 128, tid = threadIdx.x;
    for (int i = tid; i < 32 * En / 4; i += 256)
        ((float4*)&semb[0][0])[i] = ((const float4*)(emb + (size_t)vbase * En))[i];
    __syncthreads();
    int cq = tid & 31, vq = tid >> 5;
    int c = cbase + cq * 4, v0 = vq * 4;
    float acc[4][4];
    #pragma unroll
    for (int i = 0; i < 4; i++)
        #pragma unroll
        for (int j = 0; j < 4; j++) acc[i][j] = 0.0f;
    for (int e = 0; e < En; e++) {
        float4 w = *(const float4*)(Wi + (size_t)e * NG3 + c);
        #pragma unroll
        for (int vv = 0; vv < 4; vv++) {
            float a = semb[v0 + vv][e];
            acc[vv][0] = fmaf(a, w.x, acc[vv][0]);
            acc[vv][1] = fmaf(a, w.y, acc[vv][1]);
            acc[vv][2] = fmaf(a, w.z, acc[vv][2]);
            acc[vv][3] = fmaf(a, w.w, acc[vv][3]);
        }
    }
    float4 bb = make_float4(0.f, 0.f, 0.f, 0.f);
    if (c < 2 * Hn) bb = *(const float4*)(bh + c);
    #pragma unroll
    for (int vv = 0; vv < 4; vv++) {
        float4 o;
        o.x = acc[vv][0] + bb.x; o.y = acc[vv][1] + bb.y;
        o.z = acc[vv][2] + bb.z; o.w = acc[vv][3] + bb.w;
        *(float4*)(g_EW + (size_t)(vbase + v0 + vv) * NG3 + c) = o;
    }
}

// =================== weight prep: GRU B fragments (bf16 hi/lo) ===================
__global__ __launch_bounds__(256) void wprep_kernel(const float* __restrict__ Wh) {
    int nb = blockIdx.x;
    u32* dst = g_WF + (size_t)nb * BFRAG;
    for (int i = threadIdx.x; i < BFRAG; i += 256) {
        int kg = i / 384;
        int r = i - kg * 384;
        int nt = r >> 7; r &= 127;
        int l = r >> 2, c = r & 3;
        int p = c >> 1, q = c & 1;
        int k0 = kg * 16 + (l & 3) * 2 + q * 8;
        int n = nt * Hn + nb * NJb + (l >> 2);
        float w0 = Wh[(size_t)k0 * NG3 + n];
        float w1 = Wh[(size_t)(k0 + 1) * NG3 + n];
        unsigned short h0, h1;
        if (p == 0) { h0 = bf16r(w0); h1 = bf16r(w1); }
        else {
            h0 = bf16r(w0 - __bfloat162float(__ushort_as_bfloat16(bf16r(w0))));
            h1 = bf16r(w1 - __bfloat162float(__ushort_as_bfloat16(bf16r(w1))));
        }
        dst[i] = (u32)h0 | ((u32)h1 << 16);
    }
}

// =================== weight prep: Wout B fragments (bf16 hi/lo), 256 blocks ===================
__global__ __launch_bounds__(256) void woutprep_kernel(const float* __restrict__ Wout) {
    int i = blockIdx.x * 1024 + threadIdx.x;
    int iend = blockIdx.x * 1024 + 1024;
    for (; i < iend; i += 256) {
        int kg = i >> 12;
        int r = i & 4095;
        int nt = r >> 7;
        int rr = r & 127;
        int l = rr >> 2, c = rr & 3;
        int p = c >> 1, q = c & 1;
        int k0 = kg * 16 + (l & 3) * 2 + q * 8;
        int n = nt * 8 + (l >> 2);
        float w0 = Wout[(size_t)k0 * Vn + n];
        float w1 = Wout[(size_t)(k0 + 1) * Vn + n];
        unsigned short h0, h1;
        if (p == 0) { h0 = bf16r(w0); h1 = bf16r(w1); }
        else {
            h0 = bf16r(w0 - __bfloat162float(__ushort_as_bfloat16(bf16r(w0))));
            h1 = bf16r(w1 - __bfloat162float(__ushort_as_bfloat16(bf16r(w1))));
        }
        g_WOF[(size_t)kg * 4096 + r] = (u32)h0 | ((u32)h1 << 16);
    }
}

// =================== persistent mma.sync GRU (pipelined granule acquire) ===================
// 512 threads = 16 warps; warp w: mt = w&3, kq = w>>2. No __syncthreads in loop.
extern __shared__ unsigned char smem_dyn[];

__global__ __launch_bounds__(512, 1) void gru_kernel(const int* __restrict__ tokens,
                                                     const float* __restrict__ bh) {
    __shared__ float s_bh[NJb];
    __shared__ float s_part[2][3][4][32][13];   // [buf][kq-1][mt][lane][12 used]

    int tid = threadIdx.x, bid = blockIdx.x;
    int l = tid & 31, w = tid >> 5;
    int mt = w & 3, kq = w >> 2;
    int j0 = bid * NJb;
    u32 sB = smem_u32(smem_dyn);

    {
        const uint4* src = (const uint4*)(g_WF + (size_t)bid * BFRAG);
        uint4* d = (uint4*)(smem_dyn);
        for (int i = tid; i < BFRAG / 4; i += 512) d[i] = src[i];
    }
    if (tid < NJb) s_bh[tid] = bh[2 * Hn + j0 + tid];
    __syncthreads();

    int grp = l >> 2, qd = l & 3;
    int b0 = mt * 16 + grp, b1 = b0 + 8;
    int jj0 = qd * 2, jj1 = jj0 + 1;
    int colbase = (j0 & 8);
    int ksj = j0 >> 4;
    int ja = j0 + jj0;
    const u32* cg = g_cnt + (u32)((mt * 16 + kq * 4) * 32);   // 4 granules of my quarter
    u32* crel = g_cnt + (u32)((mt * 16 + (ksj >> 2)) * 32);   // producer release line

    for (int t = 0; t < Ln; t++) {
        u32 tgt = 8u * (u32)t;
        u32 pv0 = 0, pv1 = 0, pv2 = 0;   // early probes for granules 1..3

        // ---- acquire granule 0; probe granules 1-3 (results used later) ----
        if (t > 0) {
            if (l == 0) {
                while (ld_acq(cg) < tgt) { }
                pv0 = ld_acq(cg + 32);
                pv1 = ld_acq(cg + 64);
                pv2 = ld_acq(cg + 96);
            }
            __syncwarp();
        }

        const unsigned char* slab = g_YA + (size_t)t * SLAB;
        const unsigned char* ah = slab + (size_t)mt * 32768 + (size_t)kq * 8192 + (size_t)l * 16;

        // prologue: A ring = granule 0 (ks 0..3)
        uint4 rh[4], rl[4];
        #pragma unroll
        for (int p = 0; p < 4; p++) {
            rh[p] = *(const uint4*)(ah + p * 512);
            rl[p] = *(const uint4*)(ah + VERB + p * 512);
        }

        // epilogue-data prefetch (kq==0 warps)
        float2 ewr0, ewz0, ewn0, ewr1, ewz1, ewn1, hold0, hold1;
        if (kq == 0) {
            int tok0 = __ldg(tokens + b0 * Ln + t);
            int tok1 = __ldg(tokens + b1 * Ln + t);
            const float* e0 = g_EW + (size_t)tok0 * NG3;
            const float* e1 = g_EW + (size_t)tok1 * NG3;
            ewr0 = *(const float2*)(e0 + ja);
            ewz0 = *(const float2*)(e0 + Hn + ja);
            ewn0 = *(const float2*)(e0 + 2 * Hn + ja);
            ewr1 = *(const float2*)(e1 + ja);
            ewz1 = *(const float2*)(e1 + Hn + ja);
            ewn1 = *(const float2*)(e1 + 2 * Hn + ja);
            const float* hp_in = g_HP + (size_t)t * HB;
            hold0 = *(const float2*)(hp_in + (size_t)b0 * Hn + ja);
            hold1 = *(const float2*)(hp_in + (size_t)b1 * Hn + ja);
        }

        float acc[2][3][4];
        #pragma unroll
        for (int p = 0; p < 2; p++)
            #pragma unroll
            for (int nt = 0; nt < 3; nt++)
                #pragma unroll
                for (int i = 0; i < 4; i++) acc[p][nt][i] = 0.0f;

        // ---- mainloop: 4 granules, gated individually (probe-first) ----
        #pragma unroll
        for (int g = 0; g < 4; g++) {
            if (g > 0) {
                if (t > 0) {
                    u32 pv = (g == 1) ? pv0 : ((g == 2) ? pv1 : pv2);
                    if (l == 0 && pv < tgt) {
                        while (ld_acq(cg + g * 32) < tgt) { }
                    }
                    __syncwarp();
                }
            }
            #pragma unroll
            for (int s = 0; s < 4; s++) {
                int ks = g * 4 + s;
                u32 ahi[4] = { rh[s].x, rh[s].y, rh[s].z, rh[s].w };
                u32 alo[4] = { rl[s].x, rl[s].y, rl[s].z, rl[s].w };
                if (g < 3) {
                    rh[s] = *(const uint4*)(ah + (ks + 4) * 512);
                    rl[s] = *(const uint4*)(ah + VERB + (ks + 4) * 512);
                }
                int kg = kq * 16 + ks;
                int p = ks & 1;
                #pragma unroll
                for (int nt = 0; nt < 3; nt++) {
                    u32 bw0, bw1, bw2, bw3;
                    asm volatile("ld.shared.v4.u32 {%0,%1,%2,%3}, [%4];"
                        : "=r"(bw0), "=r"(bw1), "=r"(bw2), "=r"(bw3)
                        : "r"(sB + (u32)((((kg * 3 + nt) * 32 + l) * 4) * 4)));
                    mma_bf16(acc[p][nt], ahi, bw0, bw1);
                    mma_bf16(acc[p][nt], ahi, bw2, bw3);
                    mma_bf16(acc[p][nt], alo, bw0, bw1);
                }
            }
        }

        int buf = t & 1;
        if (kq > 0) {
            float* sp = &s_part[buf][kq - 1][mt][l][0];
            #pragma unroll
            for (int nt = 0; nt < 3; nt++)
                #pragma unroll
                for (int i = 0; i < 4; i++)
                    sp[nt * 4 + i] = acc[0][nt][i] + acc[1][nt][i];
        }
        // per-mt named barrier: kq1-3 roll into next step; kq0 does epilogue
        asm volatile("bar.sync %0, 128;" :: "r"(mt + 1) : "memory");

        if (kq == 0) {
            float ac[3][4];
            #pragma unroll
            for (int nt = 0; nt < 3; nt++)
                #pragma unroll
                for (int i = 0; i < 4; i++)
                    ac[nt][i] = acc[0][nt][i] + acc[1][nt][i]
                              + s_part[buf][0][mt][l][nt * 4 + i]
                              + s_part[buf][1][mt][l][nt * 4 + i]
                              + s_part[buf][2][mt][l][nt * 4 + i];

            float* hp_out = g_HP + (size_t)(t + 1) * HB;
            unsigned char* ya = g_YA + (size_t)(t + 1) * SLAB;
            u32 whi[2], wlo[2];
            #pragma unroll
            for (int hf = 0; hf < 2; hf++) {
                int b = hf ? b1 : b0;
                float2 er = hf ? ewr1 : ewr0;
                float2 ez = hf ? ewz1 : ewz0;
                float2 en = hf ? ewn1 : ewn0;
                float2 hold = hf ? hold1 : hold0;
                float sr0 = ac[0][hf * 2], sr1 = ac[0][hf * 2 + 1];
                float sz0 = ac[1][hf * 2], sz1 = ac[1][hf * 2 + 1];
                float sn0 = ac[2][hf * 2], sn1 = ac[2][hf * 2 + 1];
                float r0 = 1.0f / (1.0f + __expf(-(er.x + sr0)));
                float r1 = 1.0f / (1.0f + __expf(-(er.y + sr1)));
                float z0 = 1.0f / (1.0f + __expf(-(ez.x + sz0)));
                float z1 = 1.0f / (1.0f + __expf(-(ez.y + sz1)));
                float n0 = tanhf(en.x + r0 * (sn0 + s_bh[jj0]));
                float n1 = tanhf(en.y + r1 * (sn1 + s_bh[jj1]));
                float h0 = (1.0f - z0) * n0 + z0 * hold.x;
                float h1 = (1.0f - z1) * n1 + z1 * hold.y;
                *(float2*)(hp_out + (size_t)b * Hn + ja) = make_float2(h0, h1);
                unsigned short hi0 = bf16r(h0), hi1 = bf16r(h1);
                float f0 = h0 - __bfloat162float(__ushort_as_bfloat16(hi0));
                float f1 = h1 - __bfloat162float(__ushort_as_bfloat16(hi1));
                whi[hf] = (u32)hi0 | ((u32)hi1 << 16);
                wlo[hf] = (u32)bf16r(f0) | ((u32)bf16r(f1) << 16);
            }
            u32 base = (u32)(mt * 32768 + ksj * 512 + l * 16 + colbase);
            *(uint2*)(ya + base)        = make_uint2(whi[0], whi[1]);
            *(uint2*)(ya + VERB + base) = make_uint2(wlo[0], wlo[1]);

            __syncwarp();
            if (l == 0) red_rel(crel);
        }
    }
}

// =================== logits via mma: reads g_YA fragments + g_WOF ===================
__global__ __launch_bounds__(256, 1) void out_mma_kernel(const float* __restrict__ bout,
                                                         float* __restrict__ out) {
    __shared__ u32 sBW[2][4096];   // 2 x 16KB B-fragment chunks
    int t = blockIdx.x;
    int tid = threadIdx.x;
    int l = tid & 31, w = tid >> 5;
    int mt = w & 3, nh = w >> 2;
    int grp = l >> 2, qd = l & 3;
    u32 sb0 = smem_u32(&sBW[0][0]);

    const unsigned char* ya = g_YA + (size_t)(t + 1) * SLAB + (size_t)mt * 32768 + (size_t)l * 16;

    #pragma unroll
    for (int ks = 0; ks < 2; ks++) {
        #pragma unroll
        for (int j = 0; j < 4; j++)
            cp16(sb0 + (u32)(ks * 16384 + tid * 64 + j * 16),
                 (const unsigned char*)g_WOF + (size_t)ks * 16384 + tid * 64 + j * 16);
        cp_commit();
    }

    float acc[16][4];
    #pragma unroll
    for (int n = 0; n < 16; n++)
        #pragma unroll
        for (int i = 0; i < 4; i++) acc[n][i] = 0.0f;

    uint4 ah = *(const uint4*)(ya);
    uint4 al = *(const uint4*)(ya + VERB);

    #pragma unroll 1
    for (int ks = 0; ks < 64; ks++) {
        cp_wait<1>();
        __syncthreads();

        u32 ahi[4] = { ah.x, ah.y, ah.z, ah.w };
        u32 alo[4] = { al.x, al.y, al.z, al.w };
        if (ks < 63) {
            ah = *(const uint4*)(ya + (ks + 1) * 512);
            al = *(const uint4*)(ya + VERB + (ks + 1) * 512);
        }

        u32 sbuf = sb0 + (u32)((ks & 1) * 16384);
        #pragma unroll
        for (int n2 = 0; n2 < 16; n2++) {
            int nt = nh * 16 + n2;
            u32 bw0, bw1, bw2, bw3;
            asm volatile("ld.shared.v4.u32 {%0,%1,%2,%3}, [%4];"
                : "=r"(bw0), "=r"(bw1), "=r"(bw2), "=r"(bw3)
                : "r"(sbuf + (u32)((nt * 32 + l) * 16)));
            mma_bf16(acc[n2], ahi, bw0, bw1);
            mma_bf16(acc[n2], ahi, bw2, bw3);
            mma_bf16(acc[n2], alo, bw0, bw1);
        }
        __syncthreads();

        if (ks + 2 < 64) {
            #pragma unroll
            for (int j = 0; j < 4; j++)
                cp16(sb0 + (u32)((ks & 1) * 16384 + tid * 64 + j * 16),
                     (const unsigned char*)g_WOF + (size_t)(ks + 2) * 16384 + tid * 64 + j * 16);
        }
        cp_commit();
    }

    int b0 = mt * 16 + grp, b1 = b0 + 8;
    float* po0 = out + (size_t)b0 * Ln * Vn + (size_t)t * Vn;
    float* po1 = out + (size_t)b1 * Ln * Vn + (size_t)t * Vn;
    #pragma unroll
    for (int n2 = 0; n2 < 16; n2++) {
        int v = nh * 128 + n2 * 8 + qd * 2;
        float2 bs = *(const float2*)(bout + v);
        *(float2*)(po0 + v) = make_float2(acc[n2][0] + bs.x, acc[n2][1] + bs.y);
        *(float2*)(po1 + v) = make_float2(acc[n2][2] + bs.x, acc[n2][3] + bs.y);
    }
}

// =================== launch ===================
extern "C" void kernel_launch(void* const* d_in, const int* in_sizes, int n_in,
                              void* d_out, int out_size) {
    const int*   tokens = (const int*)d_in[0];
    const float* emb    = (const float*)d_in[1];
    const float* Wi     = (const float*)d_in[2];
    const float* Wh     = (const float*)d_in[3];
    const float* bh     = (const float*)d_in[4];
    const float* Wout   = (const float*)d_in[5];
    const float* bout   = (const float*)d_in[6];
    float* out = (float*)d_out;

    cudaFuncSetAttribute(gru_kernel, cudaFuncAttributeMaxDynamicSharedMemorySize, SMEM_DYN);

    reset_kernel<<<64, 256>>>();
    ew_kernel<<<dim3(24, 8), 256>>>(emb, Wi, bh);
    wprep_kernel<<<NBLK, 256>>>(Wh);
    woutprep_kernel<<<256, 256>>>(Wout);
    gru_kernel<<<NBLK, 512, SMEM_DYN>>>(tokens, bh);
    out_mma_kernel<<<Ln, 256>>>(bout, out);
}

// round 15
// speedup vs baseline: 1.0926x; 1.0926x over previous
#include <cuda_runtime.h>
#include <cuda_bf16.h>
#include <cstdint>

#define Bn 64
#define Ln 256
#define Vn 256
#define En 256
#define Hn 1024
#define NG3 3072
#define NBLK 128           // persistent blocks; each owns 8 hidden units
#define NJb 8
#define HB (Hn*Bn)
#define SLAB 262144        // h slab: [ver2][mt4][ks64][lane32][16B]
#define VERB 131072
#define BFRAG 24576        // u32 GRU B-fragment words per block (hi+lo)
#define SM_B 98304         // B fragments in smem (bytes)
#define SMEM_DYN SM_B

typedef unsigned int u32;
typedef unsigned long long u64;

__device__ float g_EW[Vn*NG3];                         // emb@Wi (+bh for r,z)
__device__ float g_HP[(size_t)(Ln+1)*HB];              // exact fp32 h, [t][b][j]
__device__ unsigned char g_YA[(size_t)(Ln+1)*SLAB];    // bf16 hi/lo fragment-order h
__device__ u32 g_WF[(size_t)NBLK*BFRAG];               // GRU B fragments per block
__device__ u32 g_WOF[64*32*32*4];                      // Wout B fragments (1MB)
__device__ u32 g_cnt[4*16*32];                         // (mt, ks-granule) release counters

__device__ __forceinline__ u32 smem_u32(const void* p) {
    u32 a;
    asm("{ .reg .u64 t; cvta.to.shared.u64 t, %1; cvt.u32.u64 %0, t; }" : "=r"(a) : "l"(p));
    return a;
}
__device__ __forceinline__ void cp16(u32 dst, const void* src) {
    asm volatile("cp.async.cg.shared.global [%0], [%1], 16;" :: "r"(dst), "l"(src) : "memory");
}
__device__ __forceinline__ void cp_commit() {
    asm volatile("cp.async.commit_group;" ::: "memory");
}
template<int N> __device__ __forceinline__ void cp_wait() {
    asm volatile("cp.async.wait_group %0;" :: "n"(N) : "memory");
}
__device__ __forceinline__ void mma_bf16(float* c, const u32* a, u32 b0, u32 b1) {
    asm volatile("mma.sync.aligned.m16n8k16.row.col.f32.bf16.bf16.f32 "
        "{%0,%1,%2,%3}, {%4,%5,%6,%7}, {%8,%9}, {%0,%1,%2,%3};"
        : "+f"(c[0]), "+f"(c[1]), "+f"(c[2]), "+f"(c[3])
        : "r"(a[0]), "r"(a[1]), "r"(a[2]), "r"(a[3]), "r"(b0), "r"(b1));
}
__device__ __forceinline__ unsigned short bf16r(float x) {
    return __bfloat16_as_ushort(__float2bfloat16_rn(x));
}
__device__ __forceinline__ u32 ld_acq(const u32* p) {
    u32 v;
    asm volatile("ld.acquire.gpu.global.u32 %0, [%1];" : "=r"(v) : "l"(p) : "memory");
    return v;
}
__device__ __forceinline__ void red_rel(u32* p) {
    asm volatile("red.release.gpu.global.add.u32 [%0], %1;" :: "l"(p), "r"(1u) : "memory");
}

// =================== reset ===================
__global__ void reset_kernel() {
    int tid = blockIdx.x * blockDim.x + threadIdx.x;
    int nt = gridDim.x * blockDim.x;
    for (int i = tid; i < HB; i += nt) g_HP[i] = 0.0f;
    for (int i = tid; i < SLAB / 4; i += nt) ((u32*)g_YA)[i] = 0u;
    if (tid < 4 * 16 * 32) g_cnt[tid] = 0u;
}

// =================== EW = embedding @ Wi (+ bh folded for r,z) ===================
__global__ __launch_bounds__(256) void ew_kernel(const float* __restrict__ emb,
                                                 const float* __restrict__ Wi,
                                                 const float* __restrict__ bh) {
    __shared__ float semb[32][En];
    int vbase = blockIdx.y * 32, cbase = blockIdx.x * 128, tid = threadIdx.x;
    for (int i = tid; i < 32 * En / 4; i += 256)
        ((float4*)&semb[0][0])[i] = ((const float4*)(emb + (size_t)vbase * En))[i];
    __syncthreads();
    int cq = tid & 31, vq = tid >> 5;
    int c = cbase + cq * 4, v0 = vq * 4;
    float acc[4][4];
    #pragma unroll
    for (int i = 0; i < 4; i++)
        #pragma unroll
        for (int j = 0; j < 4; j++) acc[i][j] = 0.0f;
    for (int e = 0; e < En; e++) {
        float4 w = *(const float4*)(Wi + (size_t)e * NG3 + c);
        #pragma unroll
        for (int vv = 0; vv < 4; vv++) {
            float a = semb[v0 + vv][e];
            acc[vv][0] = fmaf(a, w.x, acc[vv][0]);
            acc[vv][1] = fmaf(a, w.y, acc[vv][1]);
            acc[vv][2] = fmaf(a, w.z, acc[vv][2]);
            acc[vv][3] = fmaf(a, w.w, acc[vv][3]);
        }
    }
    float4 bb = make_float4(0.f, 0.f, 0.f, 0.f);
    if (c < 2 * Hn) bb = *(const float4*)(bh + c);
    #pragma unroll
    for (int vv = 0; vv < 4; vv++) {
        float4 o;
        o.x = acc[vv][0] + bb.x; o.y = acc[vv][1] + bb.y;
        o.z = acc[vv][2] + bb.z; o.w = acc[vv][3] + bb.w;
        *(float4*)(g_EW + (size_t)(vbase + v0 + vv) * NG3 + c) = o;
    }
}

// =================== weight prep: GRU B fragments (bf16 hi/lo) ===================
__global__ __launch_bounds__(256) void wprep_kernel(const float* __restrict__ Wh) {
    int nb = blockIdx.x;
    u32* dst = g_WF + (size_t)nb * BFRAG;
    for (int i = threadIdx.x; i < BFRAG; i += 256) {
        int kg = i / 384;
        int r = i - kg * 384;
        int nt = r >> 7; r &= 127;
        int l = r >> 2, c = r & 3;
        int p = c >> 1, q = c & 1;
        int k0 = kg * 16 + (l & 3) * 2 + q * 8;
        int n = nt * Hn + nb * NJb + (l >> 2);
        float w0 = Wh[(size_t)k0 * NG3 + n];
        float w1 = Wh[(size_t)(k0 + 1) * NG3 + n];
        unsigned short h0, h1;
        if (p == 0) { h0 = bf16r(w0); h1 = bf16r(w1); }
        else {
            h0 = bf16r(w0 - __bfloat162float(__ushort_as_bfloat16(bf16r(w0))));
            h1 = bf16r(w1 - __bfloat162float(__ushort_as_bfloat16(bf16r(w1))));
        }
        dst[i] = (u32)h0 | ((u32)h1 << 16);
    }
}

// =================== weight prep: Wout B fragments (bf16 hi/lo), 256 blocks ===================
__global__ __launch_bounds__(256) void woutprep_kernel(const float* __restrict__ Wout) {
    int i = blockIdx.x * 1024 + threadIdx.x;
    int iend = blockIdx.x * 1024 + 1024;
    for (; i < iend; i += 256) {
        int kg = i >> 12;
        int r = i & 4095;
        int nt = r >> 7;
        int rr = r & 127;
        int l = rr >> 2, c = rr & 3;
        int p = c >> 1, q = c & 1;
        int k0 = kg * 16 + (l & 3) * 2 + q * 8;
        int n = nt * 8 + (l >> 2);
        float w0 = Wout[(size_t)k0 * Vn + n];
        float w1 = Wout[(size_t)(k0 + 1) * Vn + n];
        unsigned short h0, h1;
        if (p == 0) { h0 = bf16r(w0); h1 = bf16r(w1); }
        else {
            h0 = bf16r(w0 - __bfloat162float(__ushort_as_bfloat16(bf16r(w0))));
            h1 = bf16r(w1 - __bfloat162float(__ushort_as_bfloat16(bf16r(w1))));
        }
        g_WOF[(size_t)kg * 4096 + r] = (u32)h0 | ((u32)h1 << 16);
    }
}

// =================== persistent mma.sync GRU (R13: release/acquire dataflow) ===================
// 512 threads = 16 warps; warp w: mt = w&3, kq = w>>2. No __syncthreads in loop.
// Producers: red.release per (mt, ksj>>2). Consumers: ld.acquire polls, target 8t.
// Intra-block: per-mt named barrier + double-buffered s_part.
extern __shared__ unsigned char smem_dyn[];

__global__ __launch_bounds__(512, 1) void gru_kernel(const int* __restrict__ tokens,
                                                     const float* __restrict__ bh) {
    __shared__ float s_bh[NJb];
    __shared__ float s_part[2][3][4][32][13];   // [buf][kq-1][mt][lane][12 used]

    int tid = threadIdx.x, bid = blockIdx.x;
    int l = tid & 31, w = tid >> 5;
    int mt = w & 3, kq = w >> 2;
    int j0 = bid * NJb;
    u32 sB = smem_u32(smem_dyn);

    {
        const uint4* src = (const uint4*)(g_WF + (size_t)bid * BFRAG);
        uint4* d = (uint4*)(smem_dyn);
        for (int i = tid; i < BFRAG / 4; i += 512) d[i] = src[i];
    }
    if (tid < NJb) s_bh[tid] = bh[2 * Hn + j0 + tid];
    __syncthreads();

    int grp = l >> 2, qd = l & 3;
    int b0 = mt * 16 + grp, b1 = b0 + 8;
    int jj0 = qd * 2, jj1 = jj0 + 1;
    int colbase = (j0 & 8);
    int ksj = j0 >> 4;
    int ja = j0 + jj0;
    // consumer poll address (lanes 0-3 watch the 4 granules of this kq quarter)
    const u32* cpoll = g_cnt + (u32)((mt * 16 + kq * 4 + (l & 3)) * 32);
    // producer release address
    u32* crel = g_cnt + (u32)((mt * 16 + (ksj >> 2)) * 32);

    for (int t = 0; t < Ln; t++) {
        // ---- acquire-wait: my (mt, kq) quarter of slab t fully published ----
        if (t > 0) {
            u32 tgt = 8u * (u32)t;
            if (l < 4) {
                while (ld_acq(cpoll) < tgt) { }
            }
            __syncwarp();
        }

        const unsigned char* slab = g_YA + (size_t)t * SLAB;
        const unsigned char* ah = slab + (size_t)mt * 32768 + (size_t)kq * 8192 + (size_t)l * 16;

        // prologue: A ring (depth 4)
        uint4 rh[4], rl[4];
        #pragma unroll
        for (int p = 0; p < 4; p++) {
            rh[p] = *(const uint4*)(ah + p * 512);
            rl[p] = *(const uint4*)(ah + VERB + p * 512);
        }

        // epilogue-data prefetch (kq==0 warps)
        float2 ewr0, ewz0, ewn0, ewr1, ewz1, ewn1, hold0, hold1;
        if (kq == 0) {
            int tok0 = __ldg(tokens + b0 * Ln + t);
            int tok1 = __ldg(tokens + b1 * Ln + t);
            const float* e0 = g_EW + (size_t)tok0 * NG3;
            const float* e1 = g_EW + (size_t)tok1 * NG3;
            ewr0 = *(const float2*)(e0 + ja);
            ewz0 = *(const float2*)(e0 + Hn + ja);
            ewn0 = *(const float2*)(e0 + 2 * Hn + ja);
            ewr1 = *(const float2*)(e1 + ja);
            ewz1 = *(const float2*)(e1 + Hn + ja);
            ewn1 = *(const float2*)(e1 + 2 * Hn + ja);
            const float* hp_in = g_HP + (size_t)t * HB;
            hold0 = *(const float2*)(hp_in + (size_t)b0 * Hn + ja);
            hold1 = *(const float2*)(hp_in + (size_t)b1 * Hn + ja);
        }

        float acc[2][3][4];
        #pragma unroll
        for (int p = 0; p < 2; p++)
            #pragma unroll
            for (int nt = 0; nt < 3; nt++)
                #pragma unroll
                for (int i = 0; i < 4; i++) acc[p][nt][i] = 0.0f;

        #pragma unroll
        for (int ks = 0; ks < 16; ks++) {
            int s = ks & 3;
            u32 ahi[4] = { rh[s].x, rh[s].y, rh[s].z, rh[s].w };
            u32 alo[4] = { rl[s].x, rl[s].y, rl[s].z, rl[s].w };
            if (ks < 12) {
                rh[s] = *(const uint4*)(ah + (ks + 4) * 512);
                rl[s] = *(const uint4*)(ah + VERB + (ks + 4) * 512);
            }
            int kg = kq * 16 + ks;
            int p = ks & 1;
            #pragma unroll
            for (int nt = 0; nt < 3; nt++) {
                u32 bw0, bw1, bw2, bw3;
                asm volatile("ld.shared.v4.u32 {%0,%1,%2,%3}, [%4];"
                    : "=r"(bw0), "=r"(bw1), "=r"(bw2), "=r"(bw3)
                    : "r"(sB + (u32)((((kg * 3 + nt) * 32 + l) * 4) * 4)));
                mma_bf16(acc[p][nt], ahi, bw0, bw1);
                mma_bf16(acc[p][nt], ahi, bw2, bw3);
                mma_bf16(acc[p][nt], alo, bw0, bw1);
            }
        }

        int buf = t & 1;
        if (kq > 0) {
            float* sp = &s_part[buf][kq - 1][mt][l][0];
            #pragma unroll
            for (int nt = 0; nt < 3; nt++)
                #pragma unroll
                for (int i = 0; i < 4; i++)
                    sp[nt * 4 + i] = acc[0][nt][i] + acc[1][nt][i];
        }
        // per-mt named barrier: kq1-3 roll into next step; kq0 does epilogue
        asm volatile("bar.sync %0, 128;" :: "r"(mt + 1) : "memory");

        if (kq == 0) {
            float ac[3][4];
            #pragma unroll
            for (int nt = 0; nt < 3; nt++)
                #pragma unroll
                for (int i = 0; i < 4; i++)
                    ac[nt][i] = acc[0][nt][i] + acc[1][nt][i]
                              + s_part[buf][0][mt][l][nt * 4 + i]
                              + s_part[buf][1][mt][l][nt * 4 + i]
                              + s_part[buf][2][mt][l][nt * 4 + i];

            float* hp_out = g_HP + (size_t)(t + 1) * HB;
            unsigned char* ya = g_YA + (size_t)(t + 1) * SLAB;
            u32 whi[2], wlo[2];
            #pragma unroll
            for (int hf = 0; hf < 2; hf++) {
                int b = hf ? b1 : b0;
                float2 er = hf ? ewr1 : ewr0;
                float2 ez = hf ? ewz1 : ewz0;
                float2 en = hf ? ewn1 : ewn0;
                float2 hold = hf ? hold1 : hold0;
                float sr0 = ac[0][hf * 2], sr1 = ac[0][hf * 2 + 1];
                float sz0 = ac[1][hf * 2], sz1 = ac[1][hf * 2 + 1];
                float sn0 = ac[2][hf * 2], sn1 = ac[2][hf * 2 + 1];
                float r0 = 1.0f / (1.0f + __expf(-(er.x + sr0)));
                float r1 = 1.0f / (1.0f + __expf(-(er.y + sr1)));
                float z0 = 1.0f / (1.0f + __expf(-(ez.x + sz0)));
                float z1 = 1.0f / (1.0f + __expf(-(ez.y + sz1)));
                float n0 = tanhf(en.x + r0 * (sn0 + s_bh[jj0]));
                float n1 = tanhf(en.y + r1 * (sn1 + s_bh[jj1]));
                float h0 = (1.0f - z0) * n0 + z0 * hold.x;
                float h1 = (1.0f - z1) * n1 + z1 * hold.y;
                *(float2*)(hp_out + (size_t)b * Hn + ja) = make_float2(h0, h1);
                unsigned short hi0 = bf16r(h0), hi1 = bf16r(h1);
                float f0 = h0 - __bfloat162float(__ushort_as_bfloat16(hi0));
                float f1 = h1 - __bfloat162float(__ushort_as_bfloat16(hi1));
                whi[hf] = (u32)hi0 | ((u32)hi1 << 16);
                wlo[hf] = (u32)bf16r(f0) | ((u32)bf16r(f1) << 16);
            }
            u32 base = (u32)(mt * 32768 + ksj * 512 + l * 16 + colbase);
            *(uint2*)(ya + base)        = make_uint2(whi[0], whi[1]);
            *(uint2*)(ya + VERB + base) = make_uint2(wlo[0], wlo[1]);

            // publish: warp-converged writes, then one release-add by lane 0
            __syncwarp();
            if (l == 0) red_rel(crel);
        }
    }
}

// =================== logits via mma: reads g_YA fragments + g_WOF ===================
__global__ __launch_bounds__(256, 1) void out_mma_kernel(const float* __restrict__ bout,
                                                         float* __restrict__ out) {
    __shared__ u32 sBW[2][4096];   // 2 x 16KB B-fragment chunks
    int t = blockIdx.x;
    int tid = threadIdx.x;
    int l = tid & 31, w = tid >> 5;
    int mt = w & 3, nh = w >> 2;
    int grp = l >> 2, qd = l & 3;
    u32 sb0 = smem_u32(&sBW[0][0]);

    const unsigned char* ya = g_YA + (size_t)(t + 1) * SLAB + (size_t)mt * 32768 + (size_t)l * 16;

    #pragma unroll
    for (int ks = 0; ks < 2; ks++) {
        #pragma unroll
        for (int j = 0; j < 4; j++)
            cp16(sb0 + (u32)(ks * 16384 + tid * 64 + j * 16),
                 (const unsigned char*)g_WOF + (size_t)ks * 16384 + tid * 64 + j * 16);
        cp_commit();
    }

    float acc[16][4];
    #pragma unroll
    for (int n = 0; n < 16; n++)
        #pragma unroll
        for (int i = 0; i < 4; i++) acc[n][i] = 0.0f;

    uint4 ah = *(const uint4*)(ya);
    uint4 al = *(const uint4*)(ya + VERB);

    #pragma unroll 1
    for (int ks = 0; ks < 64; ks++) {
        cp_wait<1>();
        __syncthreads();

        u32 ahi[4] = { ah.x, ah.y, ah.z, ah.w };
        u32 alo[4] = { al.x, al.y, al.z, al.w };
        if (ks < 63) {
            ah = *(const uint4*)(ya + (ks + 1) * 512);
            al = *(const uint4*)(ya + VERB + (ks + 1) * 512);
        }

        u32 sbuf = sb0 + (u32)((ks & 1) * 16384);
        #pragma unroll
        for (int n2 = 0; n2 < 16; n2++) {
            int nt = nh * 16 + n2;
            u32 bw0, bw1, bw2, bw3;
            asm volatile("ld.shared.v4.u32 {%0,%1,%2,%3}, [%4];"
                : "=r"(bw0), "=r"(bw1), "=r"(bw2), "=r"(bw3)
                : "r"(sbuf + (u32)((nt * 32 + l) * 16)));
            mma_bf16(acc[n2], ahi, bw0, bw1);
            mma_bf16(acc[n2], ahi, bw2, bw3);
            mma_bf16(acc[n2], alo, bw0, bw1);
        }
        __syncthreads();

        if (ks + 2 < 64) {
            #pragma unroll
            for (int j = 0; j < 4; j++)
                cp16(sb0 + (u32)((ks & 1) * 16384 + tid * 64 + j * 16),
                     (const unsigned char*)g_WOF + (size_t)(ks + 2) * 16384 + tid * 64 + j * 16);
        }
        cp_commit();
    }

    int b0 = mt * 16 + grp, b1 = b0 + 8;
    float* po0 = out + (size_t)b0 * Ln * Vn + (size_t)t * Vn;
    float* po1 = out + (size_t)b1 * Ln * Vn + (size_t)t * Vn;
    #pragma unroll
    for (int n2 = 0; n2 < 16; n2++) {
        int v = nh * 128 + n2 * 8 + qd * 2;
        float2 bs = *(const float2*)(bout + v);
        *(float2*)(po0 + v) = make_float2(acc[n2][0] + bs.x, acc[n2][1] + bs.y);
        *(float2*)(po1 + v) = make_float2(acc[n2][2] + bs.x, acc[n2][3] + bs.y);
    }
}

// =================== launch ===================
extern "C" void kernel_launch(void* const* d_in, const int* in_sizes, int n_in,
                              void* d_out, int out_size) {
    const int*   tokens = (const int*)d_in[0];
    const float* emb    = (const float*)d_in[1];
    const float* Wi     = (const float*)d_in[2];
    const float* Wh     = (const float*)d_in[3];
    const float* bh     = (const float*)d_in[4];
    const float* Wout   = (const float*)d_in[5];
    const float* bout   = (const float*)d_in[6];
    float* out = (float*)d_out;

    cudaFuncSetAttribute(gru_kernel, cudaFuncAttributeMaxDynamicSharedMemorySize, SMEM_DYN);

    reset_kernel<<<64, 256>>>();
    ew_kernel<<<dim3(24, 8), 256>>>(emb, Wi, bh);
    wprep_kernel<<<NBLK, 256>>>(Wh);
    woutprep_kernel<<<256, 256>>>(Wout);
    gru_kernel<<<NBLK, 512, SMEM_DYN>>>(tokens, bh);
    out_mma_kernel<<<Ln, 256>>>(bout, out);
}

// round 16
// speedup vs baseline: 1.0999x; 1.0067x over previous
#include <cuda_runtime.h>
#include <cuda_bf16.h>
#include <cstdint>

#define Bn 64
#define Ln 256
#define Vn 256
#define En 256
#define Hn 1024
#define NG3 3072
#define NBLK 128           // persistent blocks; each owns 8 hidden units
#define NJb 8
#define HB (Hn*Bn)
#define SLAB 262144        // h slab: [ver2][mt4][ks64][lane32][16B]
#define VERB 131072
#define BFRAG 24576        // u32 GRU B-fragment words per block (hi+lo)
#define SM_B 98304         // B fragments in smem (bytes)
#define SMEM_DYN SM_B

typedef unsigned int u32;
typedef unsigned long long u64;

__device__ float g_EW[Vn*NG3];                         // emb@Wi (+bh for r,z)
__device__ float g_HP[(size_t)(Ln+1)*HB];              // exact fp32 h, [t][b][j]
__device__ unsigned char g_YA[(size_t)(Ln+1)*SLAB];    // bf16 hi/lo fragment-order h
__device__ u32 g_WF[(size_t)NBLK*BFRAG];               // GRU B fragments per block
__device__ u32 g_WOF[64*32*32*4];                      // Wout B fragments (1MB)
__device__ u32 g_cnt[4*16*32];                         // (mt, ks-granule) release counters

__device__ __forceinline__ u32 smem_u32(const void* p) {
    u32 a;
    asm("{ .reg .u64 t; cvta.to.shared.u64 t, %1; cvt.u32.u64 %0, t; }" : "=r"(a) : "l"(p));
    return a;
}
__device__ __forceinline__ void cp16(u32 dst, const void* src) {
    asm volatile("cp.async.cg.shared.global [%0], [%1], 16;" :: "r"(dst), "l"(src) : "memory");
}
__device__ __forceinline__ void cp_commit() {
    asm volatile("cp.async.commit_group;" ::: "memory");
}
template<int N> __device__ __forceinline__ void cp_wait() {
    asm volatile("cp.async.wait_group %0;" :: "n"(N) : "memory");
}
__device__ __forceinline__ void mma_bf16(float* c, const u32* a, u32 b0, u32 b1) {
    asm volatile("mma.sync.aligned.m16n8k16.row.col.f32.bf16.bf16.f32 "
        "{%0,%1,%2,%3}, {%4,%5,%6,%7}, {%8,%9}, {%0,%1,%2,%3};"
        : "+f"(c[0]), "+f"(c[1]), "+f"(c[2]), "+f"(c[3])
        : "r"(a[0]), "r"(a[1]), "r"(a[2]), "r"(a[3]), "r"(b0), "r"(b1));
}
__device__ __forceinline__ unsigned short bf16r(float x) {
    return __bfloat16_as_ushort(__float2bfloat16_rn(x));
}
__device__ __forceinline__ u32 ld_acq(const u32* p) {
    u32 v;
    asm volatile("ld.acquire.gpu.global.u32 %0, [%1];" : "=r"(v) : "l"(p) : "memory");
    return v;
}
__device__ __forceinline__ void red_rel(u32* p) {
    asm volatile("red.release.gpu.global.add.u32 [%0], %1;" :: "l"(p), "r"(1u) : "memory");
}
// fast tanh via ex2-based __expf; saturates correctly for |x| large
__device__ __forceinline__ float ftanh(float x) {
    float e = __expf(2.0f * x);
    return 1.0f - __fdividef(2.0f, e + 1.0f);
}

// =================== reset ===================
__global__ void reset_kernel() {
    int tid = blockIdx.x * blockDim.x + threadIdx.x;
    int nt = gridDim.x * blockDim.x;
    for (int i = tid; i < HB; i += nt) g_HP[i] = 0.0f;
    for (int i = tid; i < SLAB / 4; i += nt) ((u32*)g_YA)[i] = 0u;
    if (tid < 4 * 16 * 32) g_cnt[tid] = 0u;
}

// =================== EW = embedding @ Wi (+ bh folded for r,z) ===================
__global__ __launch_bounds__(256) void ew_kernel(const float* __restrict__ emb,
                                                 const float* __restrict__ Wi,
                                                 const float* __restrict__ bh) {
    __shared__ float semb[32][En];
    int vbase = blockIdx.y * 32, cbase = blockIdx.x * 128, tid = threadIdx.x;
    for (int i = tid; i < 32 * En / 4; i += 256)
        ((float4*)&semb[0][0])[i] = ((const float4*)(emb + (size_t)vbase * En))[i];
    __syncthreads();
    int cq = tid & 31, vq = tid >> 5;
    int c = cbase + cq * 4, v0 = vq * 4;
    float acc[4][4];
    #pragma unroll
    for (int i = 0; i < 4; i++)
        #pragma unroll
        for (int j = 0; j < 4; j++) acc[i][j] = 0.0f;
    for (int e = 0; e < En; e++) {
        float4 w = *(const float4*)(Wi + (size_t)e * NG3 + c);
        #pragma unroll
        for (int vv = 0; vv < 4; vv++) {
            float a = semb[v0 + vv][e];
            acc[vv][0] = fmaf(a, w.x, acc[vv][0]);
            acc[vv][1] = fmaf(a, w.y, acc[vv][1]);
            acc[vv][2] = fmaf(a, w.z, acc[vv][2]);
            acc[vv][3] = fmaf(a, w.w, acc[vv][3]);
        }
    }
    float4 bb = make_float4(0.f, 0.f, 0.f, 0.f);
    if (c < 2 * Hn) bb = *(const float4*)(bh + c);
    #pragma unroll
    for (int vv = 0; vv < 4; vv++) {
        float4 o;
        o.x = acc[vv][0] + bb.x; o.y = acc[vv][1] + bb.y;
        o.z = acc[vv][2] + bb.z; o.w = acc[vv][3] + bb.w;
        *(float4*)(g_EW + (size_t)(vbase + v0 + vv) * NG3 + c) = o;
    }
}

// =================== weight prep: GRU B fragments (bf16 hi/lo) ===================
__global__ __launch_bounds__(256) void wprep_kernel(const float* __restrict__ Wh) {
    int nb = blockIdx.x;
    u32* dst = g_WF + (size_t)nb * BFRAG;
    for (int i = threadIdx.x; i < BFRAG; i += 256) {
        int kg = i / 384;
        int r = i - kg * 384;
        int nt = r >> 7; r &= 127;
        int l = r >> 2, c = r & 3;
        int p = c >> 1, q = c & 1;
        int k0 = kg * 16 + (l & 3) * 2 + q * 8;
        int n = nt * Hn + nb * NJb + (l >> 2);
        float w0 = Wh[(size_t)k0 * NG3 + n];
        float w1 = Wh[(size_t)(k0 + 1) * NG3 + n];
        unsigned short h0, h1;
        if (p == 0) { h0 = bf16r(w0); h1 = bf16r(w1); }
        else {
            h0 = bf16r(w0 - __bfloat162float(__ushort_as_bfloat16(bf16r(w0))));
            h1 = bf16r(w1 - __bfloat162float(__ushort_as_bfloat16(bf16r(w1))));
        }
        dst[i] = (u32)h0 | ((u32)h1 << 16);
    }
}

// =================== weight prep: Wout B fragments (bf16 hi/lo), 256 blocks ===================
__global__ __launch_bounds__(256) void woutprep_kernel(const float* __restrict__ Wout) {
    int i = blockIdx.x * 1024 + threadIdx.x;
    int iend = blockIdx.x * 1024 + 1024;
    for (; i < iend; i += 256) {
        int kg = i >> 12;
        int r = i & 4095;
        int nt = r >> 7;
        int rr = r & 127;
        int l = rr >> 2, c = rr & 3;
        int p = c >> 1, q = c & 1;
        int k0 = kg * 16 + (l & 3) * 2 + q * 8;
        int n = nt * 8 + (l >> 2);
        float w0 = Wout[(size_t)k0 * Vn + n];
        float w1 = Wout[(size_t)(k0 + 1) * Vn + n];
        unsigned short h0, h1;
        if (p == 0) { h0 = bf16r(w0); h1 = bf16r(w1); }
        else {
            h0 = bf16r(w0 - __bfloat162float(__ushort_as_bfloat16(bf16r(w0))));
            h1 = bf16r(w1 - __bfloat162float(__ushort_as_bfloat16(bf16r(w1))));
        }
        g_WOF[(size_t)kg * 4096 + r] = (u32)h0 | ((u32)h1 << 16);
    }
}

// =================== persistent mma.sync GRU (R13: release/acquire dataflow) ===================
// 512 threads = 16 warps; warp w: mt = w&3, kq = w>>2. No __syncthreads in loop.
extern __shared__ unsigned char smem_dyn[];

__global__ __launch_bounds__(512, 1) void gru_kernel(const int* __restrict__ tokens,
                                                     const float* __restrict__ bh) {
    __shared__ float s_bh[NJb];
    __shared__ float s_part[2][3][4][32][13];   // [buf][kq-1][mt][lane][12 used]

    int tid = threadIdx.x, bid = blockIdx.x;
    int l = tid & 31, w = tid >> 5;
    int mt = w & 3, kq = w >> 2;
    int j0 = bid * NJb;
    u32 sB = smem_u32(smem_dyn);

    {
        const uint4* src = (const uint4*)(g_WF + (size_t)bid * BFRAG);
        uint4* d = (uint4*)(smem_dyn);
        for (int i = tid; i < BFRAG / 4; i += 512) d[i] = src[i];
    }
    if (tid < NJb) s_bh[tid] = bh[2 * Hn + j0 + tid];
    __syncthreads();

    int grp = l >> 2, qd = l & 3;
    int b0 = mt * 16 + grp, b1 = b0 + 8;
    int jj0 = qd * 2, jj1 = jj0 + 1;
    int colbase = (j0 & 8);
    int ksj = j0 >> 4;
    int ja = j0 + jj0;
    const u32* cpoll = g_cnt + (u32)((mt * 16 + kq * 4 + (l & 3)) * 32);
    u32* crel = g_cnt + (u32)((mt * 16 + (ksj >> 2)) * 32);

    for (int t = 0; t < Ln; t++) {
        if (t > 0) {
            u32 tgt = 8u * (u32)t;
            if (l < 4) {
                while (ld_acq(cpoll) < tgt) { }
            }
            __syncwarp();
        }

        const unsigned char* slab = g_YA + (size_t)t * SLAB;
        const unsigned char* ah = slab + (size_t)mt * 32768 + (size_t)kq * 8192 + (size_t)l * 16;

        uint4 rh[4], rl[4];
        #pragma unroll
        for (int p = 0; p < 4; p++) {
            rh[p] = *(const uint4*)(ah + p * 512);
            rl[p] = *(const uint4*)(ah + VERB + p * 512);
        }

        float2 ewr0, ewz0, ewn0, ewr1, ewz1, ewn1, hold0, hold1;
        if (kq == 0) {
            int tok0 = __ldg(tokens + b0 * Ln + t);
            int tok1 = __ldg(tokens + b1 * Ln + t);
            const float* e0 = g_EW + (size_t)tok0 * NG3;
            const float* e1 = g_EW + (size_t)tok1 * NG3;
            ewr0 = *(const float2*)(e0 + ja);
            ewz0 = *(const float2*)(e0 + Hn + ja);
            ewn0 = *(const float2*)(e0 + 2 * Hn + ja);
            ewr1 = *(const float2*)(e1 + ja);
            ewz1 = *(const float2*)(e1 + Hn + ja);
            ewn1 = *(const float2*)(e1 + 2 * Hn + ja);
            const float* hp_in = g_HP + (size_t)t * HB;
            hold0 = *(const float2*)(hp_in + (size_t)b0 * Hn + ja);
            hold1 = *(const float2*)(hp_in + (size_t)b1 * Hn + ja);
        }

        float acc[2][3][4];
        #pragma unroll
        for (int p = 0; p < 2; p++)
            #pragma unroll
            for (int nt = 0; nt < 3; nt++)
                #pragma unroll
                for (int i = 0; i < 4; i++) acc[p][nt][i] = 0.0f;

        #pragma unroll
        for (int ks = 0; ks < 16; ks++) {
            int s = ks & 3;
            u32 ahi[4] = { rh[s].x, rh[s].y, rh[s].z, rh[s].w };
            u32 alo[4] = { rl[s].x, rl[s].y, rl[s].z, rl[s].w };
            if (ks < 12) {
                rh[s] = *(const uint4*)(ah + (ks + 4) * 512);
                rl[s] = *(const uint4*)(ah + VERB + (ks + 4) * 512);
            }
            int kg = kq * 16 + ks;
            int p = ks & 1;
            #pragma unroll
            for (int nt = 0; nt < 3; nt++) {
                u32 bw0, bw1, bw2, bw3;
                asm volatile("ld.shared.v4.u32 {%0,%1,%2,%3}, [%4];"
                    : "=r"(bw0), "=r"(bw1), "=r"(bw2), "=r"(bw3)
                    : "r"(sB + (u32)((((kg * 3 + nt) * 32 + l) * 4) * 4)));
                mma_bf16(acc[p][nt], ahi, bw0, bw1);
                mma_bf16(acc[p][nt], ahi, bw2, bw3);
                mma_bf16(acc[p][nt], alo, bw0, bw1);
            }
        }

        int buf = t & 1;
        if (kq > 0) {
            float* sp = &s_part[buf][kq - 1][mt][l][0];
            #pragma unroll
            for (int nt = 0; nt < 3; nt++)
                #pragma unroll
                for (int i = 0; i < 4; i++)
                    sp[nt * 4 + i] = acc[0][nt][i] + acc[1][nt][i];
        }
        asm volatile("bar.sync %0, 128;" :: "r"(mt + 1) : "memory");

        if (kq == 0) {
            float ac[3][4];
            #pragma unroll
            for (int nt = 0; nt < 3; nt++)
                #pragma unroll
                for (int i = 0; i < 4; i++)
                    ac[nt][i] = acc[0][nt][i] + acc[1][nt][i]
                              + s_part[buf][0][mt][l][nt * 4 + i]
                              + s_part[buf][1][mt][l][nt * 4 + i]
                              + s_part[buf][2][mt][l][nt * 4 + i];

            float* hp_out = g_HP + (size_t)(t + 1) * HB;
            unsigned char* ya = g_YA + (size_t)(t + 1) * SLAB;
            u32 whi[2], wlo[2];
            #pragma unroll
            for (int hf = 0; hf < 2; hf++) {
                int b = hf ? b1 : b0;
                float2 er = hf ? ewr1 : ewr0;
                float2 ez = hf ? ewz1 : ewz0;
                float2 en = hf ? ewn1 : ewn0;
                float2 hold = hf ? hold1 : hold0;
                float sr0 = ac[0][hf * 2], sr1 = ac[0][hf * 2 + 1];
                float sz0 = ac[1][hf * 2], sz1 = ac[1][hf * 2 + 1];
                float sn0 = ac[2][hf * 2], sn1 = ac[2][hf * 2 + 1];
                float r0 = 1.0f / (1.0f + __expf(-(er.x + sr0)));
                float r1 = 1.0f / (1.0f + __expf(-(er.y + sr1)));
                float z0 = 1.0f / (1.0f + __expf(-(ez.x + sz0)));
                float z1 = 1.0f / (1.0f + __expf(-(ez.y + sz1)));
                float n0 = ftanh(en.x + r0 * (sn0 + s_bh[jj0]));
                float n1 = ftanh(en.y + r1 * (sn1 + s_bh[jj1]));
                float h0 = (1.0f - z0) * n0 + z0 * hold.x;
                float h1 = (1.0f - z1) * n1 + z1 * hold.y;
                *(float2*)(hp_out + (size_t)b * Hn + ja) = make_float2(h0, h1);
                unsigned short hi0 = bf16r(h0), hi1 = bf16r(h1);
                float f0 = h0 - __bfloat162float(__ushort_as_bfloat16(hi0));
                float f1 = h1 - __bfloat162float(__ushort_as_bfloat16(hi1));
                whi[hf] = (u32)hi0 | ((u32)hi1 << 16);
                wlo[hf] = (u32)bf16r(f0) | ((u32)bf16r(f1) << 16);
            }
            u32 base = (u32)(mt * 32768 + ksj * 512 + l * 16 + colbase);
            *(uint2*)(ya + base)        = make_uint2(whi[0], whi[1]);
            *(uint2*)(ya + VERB + base) = make_uint2(wlo[0], wlo[1]);

            __syncwarp();
            if (l == 0) red_rel(crel);
        }
    }
}

// =================== logits via mma: 2-ks stages, double-buffered 64KB ===================
__global__ __launch_bounds__(256, 1) void out_mma_kernel(const float* __restrict__ bout,
                                                         float* __restrict__ out) {
    __shared__ u32 sBW[2][8192];   // 2 x 32KB B-fragment stages (2 ks each)
    int t = blockIdx.x;
    int tid = threadIdx.x;
    int l = tid & 31, w = tid >> 5;
    int mt = w & 3, nh = w >> 2;
    int grp = l >> 2, qd = l & 3;
    u32 sb0 = smem_u32(&sBW[0][0]);

    const unsigned char* ya = g_YA + (size_t)(t + 1) * SLAB + (size_t)mt * 32768 + (size_t)l * 16;

    // prologue: stage 0 and stage 1 (ks 0-3)
    #pragma unroll
    for (int st = 0; st < 2; st++) {
        #pragma unroll
        for (int j = 0; j < 8; j++)
            cp16(sb0 + (u32)(st * 32768 + j * 4096 + tid * 16),
                 (const unsigned char*)g_WOF + (size_t)st * 32768 + j * 4096 + tid * 16);
        cp_commit();
    }

    float acc[16][4];
    #pragma unroll
    for (int n = 0; n < 16; n++)
        #pragma unroll
        for (int i = 0; i < 4; i++) acc[n][i] = 0.0f;

    uint4 ah = *(const uint4*)(ya);
    uint4 al = *(const uint4*)(ya + VERB);

    #pragma unroll 1
    for (int st = 0; st < 32; st++) {
        cp_wait<1>();
        __syncthreads();

        #pragma unroll
        for (int k2 = 0; k2 < 2; k2++) {
            int ks = st * 2 + k2;
            u32 ahi[4] = { ah.x, ah.y, ah.z, ah.w };
            u32 alo[4] = { al.x, al.y, al.z, al.w };
            if (ks < 63) {
                ah = *(const uint4*)(ya + (ks + 1) * 512);
                al = *(const uint4*)(ya + VERB + (ks + 1) * 512);
            }
            u32 sbuf = sb0 + (u32)((st & 1) * 32768 + k2 * 16384);
            #pragma unroll
            for (int n2 = 0; n2 < 16; n2++) {
                int nt = nh * 16 + n2;
                u32 bw0, bw1, bw2, bw3;
                asm volatile("ld.shared.v4.u32 {%0,%1,%2,%3}, [%4];"
                    : "=r"(bw0), "=r"(bw1), "=r"(bw2), "=r"(bw3)
                    : "r"(sbuf + (u32)((nt * 32 + l) * 16)));
                mma_bf16(acc[n2], ahi, bw0, bw1);
                mma_bf16(acc[n2], ahi, bw2, bw3);
                mma_bf16(acc[n2], alo, bw0, bw1);
            }
        }
        __syncthreads();

        if (st + 2 < 32) {
            #pragma unroll
            for (int j = 0; j < 8; j++)
                cp16(sb0 + (u32)((st & 1) * 32768 + j * 4096 + tid * 16),
                     (const unsigned char*)g_WOF + (size_t)(st + 2) * 32768 + j * 4096 + tid * 16);
        }
        cp_commit();   // uniform commit (possibly empty group) keeps wait counting exact
    }

    int b0 = mt * 16 + grp, b1 = b0 + 8;
    float* po0 = out + (size_t)b0 * Ln * Vn + (size_t)t * Vn;
    float* po1 = out + (size_t)b1 * Ln * Vn + (size_t)t * Vn;
    #pragma unroll
    for (int n2 = 0; n2 < 16; n2++) {
        int v = nh * 128 + n2 * 8 + qd * 2;
        float2 bs = *(const float2*)(bout + v);
        *(float2*)(po0 + v) = make_float2(acc[n2][0] + bs.x, acc[n2][1] + bs.y);
        *(float2*)(po1 + v) = make_float2(acc[n2][2] + bs.x, acc[n2][3] + bs.y);
    }
}

// =================== launch ===================
extern "C" void kernel_launch(void* const* d_in, const int* in_sizes, int n_in,
                              void* d_out, int out_size) {
    const int*   tokens = (const int*)d_in[0];
    const float* emb    = (const float*)d_in[1];
    const float* Wi     = (const float*)d_in[2];
    const float* Wh     = (const float*)d_in[3];
    const float* bh     = (const float*)d_in[4];
    const float* Wout   = (const float*)d_in[5];
    const float* bout   = (const float*)d_in[6];
    float* out = (float*)d_out;

    cudaFuncSetAttribute(gru_kernel, cudaFuncAttributeMaxDynamicSharedMemorySize, SMEM_DYN);

    reset_kernel<<<64, 256>>>();
    ew_kernel<<<dim3(24, 8), 256>>>(emb, Wi, bh);
    wprep_kernel<<<NBLK, 256>>>(Wh);
    woutprep_kernel<<<256, 256>>>(Wout);
    gru_kernel<<<NBLK, 512, SMEM_DYN>>>(tokens, bh);
    out_mma_kernel<<<Ln, 256>>>(bout, out);
}

// round 17
// speedup vs baseline: 1.1703x; 1.0640x over previous
#include <cuda_runtime.h>
#include <cuda_bf16.h>
#include <cstdint>

#define Bn 64
#define Ln 256
#define Vn 256
#define En 256
#define Hn 1024
#define NG3 3072
#define NBLK 128           // persistent GRU blocks; each owns 8 hidden units
#define NOUT 20            // out-consumer blocks (idle SMs)
#define NJb 8
#define HB (Hn*Bn)
#define SLAB 262144        // h slab: [ver2][mt4][ks64][lane32][16B]
#define VERB 131072
#define BFRAG 24576        // u32 GRU B-fragment words per block (hi+lo)
#define SM_B 98304         // B fragments in smem (bytes)
#define SMEM_DYN SM_B

typedef unsigned int u32;
typedef unsigned long long u64;

__device__ float g_EW[Vn*NG3];                         // emb@Wi (+bh for r,z)
__device__ float g_HP[(size_t)(Ln+1)*HB];              // exact fp32 h, [t][b][j]
__device__ unsigned char g_YA[(size_t)(Ln+1)*SLAB];    // bf16 hi/lo fragment-order h
__device__ u32 g_WF[(size_t)NBLK*BFRAG];               // GRU B fragments per block
__device__ u32 g_WOF[64*32*32*4];                      // Wout B fragments (1MB)
__device__ u32 g_cnt[4*16*32];                         // (mt, ks-granule) release counters

__device__ __forceinline__ u32 smem_u32(const void* p) {
    u32 a;
    asm("{ .reg .u64 t; cvta.to.shared.u64 t, %1; cvt.u32.u64 %0, t; }" : "=r"(a) : "l"(p));
    return a;
}
__device__ __forceinline__ void cp16(u32 dst, const void* src) {
    asm volatile("cp.async.cg.shared.global [%0], [%1], 16;" :: "r"(dst), "l"(src) : "memory");
}
__device__ __forceinline__ void cp_commit() {
    asm volatile("cp.async.commit_group;" ::: "memory");
}
template<int N> __device__ __forceinline__ void cp_wait() {
    asm volatile("cp.async.wait_group %0;" :: "n"(N) : "memory");
}
__device__ __forceinline__ void mma_bf16(float* c, const u32* a, u32 b0, u32 b1) {
    asm volatile("mma.sync.aligned.m16n8k16.row.col.f32.bf16.bf16.f32 "
        "{%0,%1,%2,%3}, {%4,%5,%6,%7}, {%8,%9}, {%0,%1,%2,%3};"
        : "+f"(c[0]), "+f"(c[1]), "+f"(c[2]), "+f"(c[3])
        : "r"(a[0]), "r"(a[1]), "r"(a[2]), "r"(a[3]), "r"(b0), "r"(b1));
}
__device__ __forceinline__ unsigned short bf16r(float x) {
    return __bfloat16_as_ushort(__float2bfloat16_rn(x));
}
__device__ __forceinline__ u32 ld_acq(const u32* p) {
    u32 v;
    asm volatile("ld.acquire.gpu.global.u32 %0, [%1];" : "=r"(v) : "l"(p) : "memory");
    return v;
}
__device__ __forceinline__ void red_rel(u32* p) {
    asm volatile("red.release.gpu.global.add.u32 [%0], %1;" :: "l"(p), "r"(1u) : "memory");
}
__device__ __forceinline__ float ftanh(float x) {
    float e = __expf(2.0f * x);
    return 1.0f - __fdividef(2.0f, e + 1.0f);
}

// =================== reset ===================
__global__ void reset_kernel() {
    int tid = blockIdx.x * blockDim.x + threadIdx.x;
    int nt = gridDim.x * blockDim.x;
    for (int i = tid; i < HB; i += nt) g_HP[i] = 0.0f;
    for (int i = tid; i < SLAB / 4; i += nt) ((u32*)g_YA)[i] = 0u;
    if (tid < 4 * 16 * 32) g_cnt[tid] = 0u;
}

// =================== EW = embedding @ Wi (+ bh folded for r,z) ===================
__global__ __launch_bounds__(256) void ew_kernel(const float* __restrict__ emb,
                                                 const float* __restrict__ Wi,
                                                 const float* __restrict__ bh) {
    __shared__ float semb[32][En];
    int vbase = blockIdx.y * 32, cbase = blockIdx.x * 128, tid = threadIdx.x;
    for (int i = tid; i < 32 * En / 4; i += 256)
        ((float4*)&semb[0][0])[i] = ((const float4*)(emb + (size_t)vbase * En))[i];
    __syncthreads();
    int cq = tid & 31, vq = tid >> 5;
    int c = cbase + cq * 4, v0 = vq * 4;
    float acc[4][4];
    #pragma unroll
    for (int i = 0; i < 4; i++)
        #pragma unroll
        for (int j = 0; j < 4; j++) acc[i][j] = 0.0f;
    for (int e = 0; e < En; e++) {
        float4 w = *(const float4*)(Wi + (size_t)e * NG3 + c);
        #pragma unroll
        for (int vv = 0; vv < 4; vv++) {
            float a = semb[v0 + vv][e];
            acc[vv][0] = fmaf(a, w.x, acc[vv][0]);
            acc[vv][1] = fmaf(a, w.y, acc[vv][1]);
            acc[vv][2] = fmaf(a, w.z, acc[vv][2]);
            acc[vv][3] = fmaf(a, w.w, acc[vv][3]);
        }
    }
    float4 bb = make_float4(0.f, 0.f, 0.f, 0.f);
    if (c < 2 * Hn) bb = *(const float4*)(bh + c);
    #pragma unroll
    for (int vv = 0; vv < 4; vv++) {
        float4 o;
        o.x = acc[vv][0] + bb.x; o.y = acc[vv][1] + bb.y;
        o.z = acc[vv][2] + bb.z; o.w = acc[vv][3] + bb.w;
        *(float4*)(g_EW + (size_t)(vbase + v0 + vv) * NG3 + c) = o;
    }
}

// =================== weight prep: GRU B fragments (bf16 hi/lo) ===================
__global__ __launch_bounds__(256) void wprep_kernel(const float* __restrict__ Wh) {
    int nb = blockIdx.x;
    u32* dst = g_WF + (size_t)nb * BFRAG;
    for (int i = threadIdx.x; i < BFRAG; i += 256) {
        int kg = i / 384;
        int r = i - kg * 384;
        int nt = r >> 7; r &= 127;
        int l = r >> 2, c = r & 3;
        int p = c >> 1, q = c & 1;
        int k0 = kg * 16 + (l & 3) * 2 + q * 8;
        int n = nt * Hn + nb * NJb + (l >> 2);
        float w0 = Wh[(size_t)k0 * NG3 + n];
        float w1 = Wh[(size_t)(k0 + 1) * NG3 + n];
        unsigned short h0, h1;
        if (p == 0) { h0 = bf16r(w0); h1 = bf16r(w1); }
        else {
            h0 = bf16r(w0 - __bfloat162float(__ushort_as_bfloat16(bf16r(w0))));
            h1 = bf16r(w1 - __bfloat162float(__ushort_as_bfloat16(bf16r(w1))));
        }
        dst[i] = (u32)h0 | ((u32)h1 << 16);
    }
}

// =================== weight prep: Wout B fragments (bf16 hi/lo), 256 blocks ===================
__global__ __launch_bounds__(256) void woutprep_kernel(const float* __restrict__ Wout) {
    int i = blockIdx.x * 1024 + threadIdx.x;
    int iend = blockIdx.x * 1024 + 1024;
    for (; i < iend; i += 256) {
        int kg = i >> 12;
        int r = i & 4095;
        int nt = r >> 7;
        int rr = r & 127;
        int l = rr >> 2, c = rr & 3;
        int p = c >> 1, q = c & 1;
        int k0 = kg * 16 + (l & 3) * 2 + q * 8;
        int n = nt * 8 + (l >> 2);
        float w0 = Wout[(size_t)k0 * Vn + n];
        float w1 = Wout[(size_t)(k0 + 1) * Vn + n];
        unsigned short h0, h1;
        if (p == 0) { h0 = bf16r(w0); h1 = bf16r(w1); }
        else {
            h0 = bf16r(w0 - __bfloat162float(__ushort_as_bfloat16(bf16r(w0))));
            h1 = bf16r(w1 - __bfloat162float(__ushort_as_bfloat16(bf16r(w1))));
        }
        g_WOF[(size_t)kg * 4096 + r] = (u32)h0 | ((u32)h1 << 16);
    }
}

// =================== fused persistent kernel: GRU (blocks 0-127) + out (128-147) ===================
extern __shared__ unsigned char smem_dyn[];

__global__ __launch_bounds__(512, 1) void gru_kernel(const int* __restrict__ tokens,
                                                     const float* __restrict__ bh,
                                                     const float* __restrict__ bout,
                                                     float* __restrict__ out) {
    __shared__ float s_bh[NJb];
    __shared__ float s_part[2][3][4][32][13];   // [buf][kq-1][mt][lane][12 used]

    int tid = threadIdx.x, bid = blockIdx.x;

    // ================= out-consumer path (blocks 128..147) =================
    if (bid >= NBLK) {
        if (tid >= 256) return;
        int ob = bid - NBLK;
        int l = tid & 31, w = tid >> 5;
        int mt = w & 3, nh = w >> 2;
        int grp = l >> 2, qd = l & 3;
        u32 sb0 = smem_u32(smem_dyn);   // 64KB double buffer inside 96KB region

        for (int t = ob; t < Ln; t += NOUT) {
            // wait until slab t+1 fully published (all 64 counters)
            u32 tgt = 8u * (u32)(t + 1);
            if (tid < 64) {
                while (ld_acq(g_cnt + tid * 32) < tgt) { __nanosleep(200); }
            }
            asm volatile("bar.sync 1, 256;" ::: "memory");

            const unsigned char* ya = g_YA + (size_t)(t + 1) * SLAB
                                    + (size_t)mt * 32768 + (size_t)l * 16;

            // prologue: stage 0 and 1 (2 ks each)
            #pragma unroll
            for (int st = 0; st < 2; st++) {
                #pragma unroll
                for (int j = 0; j < 8; j++)
                    cp16(sb0 + (u32)(st * 32768 + j * 4096 + tid * 16),
                         (const unsigned char*)g_WOF + (size_t)st * 32768 + j * 4096 + tid * 16);
                cp_commit();
            }

            float acc[16][4];
            #pragma unroll
            for (int n = 0; n < 16; n++)
                #pragma unroll
                for (int i = 0; i < 4; i++) acc[n][i] = 0.0f;

            uint4 ah = *(const uint4*)(ya);
            uint4 al = *(const uint4*)(ya + VERB);

            #pragma unroll 1
            for (int st = 0; st < 32; st++) {
                cp_wait<1>();
                asm volatile("bar.sync 1, 256;" ::: "memory");

                #pragma unroll
                for (int k2 = 0; k2 < 2; k2++) {
                    int ks = st * 2 + k2;
                    u32 ahi[4] = { ah.x, ah.y, ah.z, ah.w };
                    u32 alo[4] = { al.x, al.y, al.z, al.w };
                    if (ks < 63) {
                        ah = *(const uint4*)(ya + (ks + 1) * 512);
                        al = *(const uint4*)(ya + VERB + (ks + 1) * 512);
                    }
                    u32 sbuf = sb0 + (u32)((st & 1) * 32768 + k2 * 16384);
                    #pragma unroll
                    for (int n2 = 0; n2 < 16; n2++) {
                        int nt = nh * 16 + n2;
                        u32 bw0, bw1, bw2, bw3;
                        asm volatile("ld.shared.v4.u32 {%0,%1,%2,%3}, [%4];"
                            : "=r"(bw0), "=r"(bw1), "=r"(bw2), "=r"(bw3)
                            : "r"(sbuf + (u32)((nt * 32 + l) * 16)));
                        mma_bf16(acc[n2], ahi, bw0, bw1);
                        mma_bf16(acc[n2], ahi, bw2, bw3);
                        mma_bf16(acc[n2], alo, bw0, bw1);
                    }
                }
                asm volatile("bar.sync 1, 256;" ::: "memory");

                if (st + 2 < 32) {
                    #pragma unroll
                    for (int j = 0; j < 8; j++)
                        cp16(sb0 + (u32)((st & 1) * 32768 + j * 4096 + tid * 16),
                             (const unsigned char*)g_WOF + (size_t)(st + 2) * 32768 + j * 4096 + tid * 16);
                }
                cp_commit();
            }

            int b0 = mt * 16 + grp, b1 = b0 + 8;
            float* po0 = out + (size_t)b0 * Ln * Vn + (size_t)t * Vn;
            float* po1 = out + (size_t)b1 * Ln * Vn + (size_t)t * Vn;
            #pragma unroll
            for (int n2 = 0; n2 < 16; n2++) {
                int v = nh * 128 + n2 * 8 + qd * 2;
                float2 bs = *(const float2*)(bout + v);
                *(float2*)(po0 + v) = make_float2(acc[n2][0] + bs.x, acc[n2][1] + bs.y);
                *(float2*)(po1 + v) = make_float2(acc[n2][2] + bs.x, acc[n2][3] + bs.y);
            }
        }
        return;
    }

    // ================= GRU path (blocks 0..127), R13 protocol =================
    int l = tid & 31, w = tid >> 5;
    int mt = w & 3, kq = w >> 2;
    int j0 = bid * NJb;
    u32 sB = smem_u32(smem_dyn);

    {
        const uint4* src = (const uint4*)(g_WF + (size_t)bid * BFRAG);
        uint4* d = (uint4*)(smem_dyn);
        for (int i = tid; i < BFRAG / 4; i += 512) d[i] = src[i];
    }
    if (tid < NJb) s_bh[tid] = bh[2 * Hn + j0 + tid];
    __syncthreads();

    int grp = l >> 2, qd = l & 3;
    int b0 = mt * 16 + grp, b1 = b0 + 8;
    int jj0 = qd * 2, jj1 = jj0 + 1;
    int colbase = (j0 & 8);
    int ksj = j0 >> 4;
    int ja = j0 + jj0;
    const u32* cpoll = g_cnt + (u32)((mt * 16 + kq * 4 + (l & 3)) * 32);
    u32* crel = g_cnt + (u32)((mt * 16 + (ksj >> 2)) * 32);

    for (int t = 0; t < Ln; t++) {
        if (t > 0) {
            u32 tgt = 8u * (u32)t;
            if (l < 4) {
                while (ld_acq(cpoll) < tgt) { }
            }
            __syncwarp();
        }

        const unsigned char* slab = g_YA + (size_t)t * SLAB;
        const unsigned char* ah = slab + (size_t)mt * 32768 + (size_t)kq * 8192 + (size_t)l * 16;

        uint4 rh[4], rl[4];
        #pragma unroll
        for (int p = 0; p < 4; p++) {
            rh[p] = *(const uint4*)(ah + p * 512);
            rl[p] = *(const uint4*)(ah + VERB + p * 512);
        }

        float2 ewr0, ewz0, ewn0, ewr1, ewz1, ewn1, hold0, hold1;
        if (kq == 0) {
            int tok0 = __ldg(tokens + b0 * Ln + t);
            int tok1 = __ldg(tokens + b1 * Ln + t);
            const float* e0 = g_EW + (size_t)tok0 * NG3;
            const float* e1 = g_EW + (size_t)tok1 * NG3;
            ewr0 = *(const float2*)(e0 + ja);
            ewz0 = *(const float2*)(e0 + Hn + ja);
            ewn0 = *(const float2*)(e0 + 2 * Hn + ja);
            ewr1 = *(const float2*)(e1 + ja);
            ewz1 = *(const float2*)(e1 + Hn + ja);
            ewn1 = *(const float2*)(e1 + 2 * Hn + ja);
            const float* hp_in = g_HP + (size_t)t * HB;
            hold0 = *(const float2*)(hp_in + (size_t)b0 * Hn + ja);
            hold1 = *(const float2*)(hp_in + (size_t)b1 * Hn + ja);
        }

        float acc[2][3][4];
        #pragma unroll
        for (int p = 0; p < 2; p++)
            #pragma unroll
            for (int nt = 0; nt < 3; nt++)
                #pragma unroll
                for (int i = 0; i < 4; i++) acc[p][nt][i] = 0.0f;

        #pragma unroll
        for (int ks = 0; ks < 16; ks++) {
            int s = ks & 3;
            u32 ahi[4] = { rh[s].x, rh[s].y, rh[s].z, rh[s].w };
            u32 alo[4] = { rl[s].x, rl[s].y, rl[s].z, rl[s].w };
            if (ks < 12) {
                rh[s] = *(const uint4*)(ah + (ks + 4) * 512);
                rl[s] = *(const uint4*)(ah + VERB + (ks + 4) * 512);
            }
            int kg = kq * 16 + ks;
            int p = ks & 1;
            #pragma unroll
            for (int nt = 0; nt < 3; nt++) {
                u32 bw0, bw1, bw2, bw3;
                asm volatile("ld.shared.v4.u32 {%0,%1,%2,%3}, [%4];"
                    : "=r"(bw0), "=r"(bw1), "=r"(bw2), "=r"(bw3)
                    : "r"(sB + (u32)((((kg * 3 + nt) * 32 + l) * 4) * 4)));
                mma_bf16(acc[p][nt], ahi, bw0, bw1);
                mma_bf16(acc[p][nt], ahi, bw2, bw3);
                mma_bf16(acc[p][nt], alo, bw0, bw1);
            }
        }

        int buf = t & 1;
        if (kq > 0) {
            float* sp = &s_part[buf][kq - 1][mt][l][0];
            #pragma unroll
            for (int nt = 0; nt < 3; nt++)
                #pragma unroll
                for (int i = 0; i < 4; i++)
                    sp[nt * 4 + i] = acc[0][nt][i] + acc[1][nt][i];
        }
        asm volatile("bar.sync %0, 128;" :: "r"(mt + 1) : "memory");

        if (kq == 0) {
            float ac[3][4];
            #pragma unroll
            for (int nt = 0; nt < 3; nt++)
                #pragma unroll
                for (int i = 0; i < 4; i++)
                    ac[nt][i] = acc[0][nt][i] + acc[1][nt][i]
                              + s_part[buf][0][mt][l][nt * 4 + i]
                              + s_part[buf][1][mt][l][nt * 4 + i]
                              + s_part[buf][2][mt][l][nt * 4 + i];

            float* hp_out = g_HP + (size_t)(t + 1) * HB;
            unsigned char* ya = g_YA + (size_t)(t + 1) * SLAB;
            u32 whi[2], wlo[2];
            #pragma unroll
            for (int hf = 0; hf < 2; hf++) {
                int b = hf ? b1 : b0;
                float2 er = hf ? ewr1 : ewr0;
                float2 ez = hf ? ewz1 : ewz0;
                float2 en = hf ? ewn1 : ewn0;
                float2 hold = hf ? hold1 : hold0;
                float sr0 = ac[0][hf * 2], sr1 = ac[0][hf * 2 + 1];
                float sz0 = ac[1][hf * 2], sz1 = ac[1][hf * 2 + 1];
                float sn0 = ac[2][hf * 2], sn1 = ac[2][hf * 2 + 1];
                float r0 = 1.0f / (1.0f + __expf(-(er.x + sr0)));
                float r1 = 1.0f / (1.0f + __expf(-(er.y + sr1)));
                float z0 = 1.0f / (1.0f + __expf(-(ez.x + sz0)));
                float z1 = 1.0f / (1.0f + __expf(-(ez.y + sz1)));
                float n0 = ftanh(en.x + r0 * (sn0 + s_bh[jj0]));
                float n1 = ftanh(en.y + r1 * (sn1 + s_bh[jj1]));
                float h0 = (1.0f - z0) * n0 + z0 * hold.x;
                float h1 = (1.0f - z1) * n1 + z1 * hold.y;
                *(float2*)(hp_out + (size_t)b * Hn + ja) = make_float2(h0, h1);
                unsigned short hi0 = bf16r(h0), hi1 = bf16r(h1);
                float f0 = h0 - __bfloat162float(__ushort_as_bfloat16(hi0));
                float f1 = h1 - __bfloat162float(__ushort_as_bfloat16(hi1));
                whi[hf] = (u32)hi0 | ((u32)hi1 << 16);
                wlo[hf] = (u32)bf16r(f0) | ((u32)bf16r(f1) << 16);
            }
            u32 base = (u32)(mt * 32768 + ksj * 512 + l * 16 + colbase);
            *(uint2*)(ya + base)        = make_uint2(whi[0], whi[1]);
            *(uint2*)(ya + VERB + base) = make_uint2(wlo[0], wlo[1]);

            __syncwarp();
            if (l == 0) red_rel(crel);
        }
    }
}

// =================== launch ===================
extern "C" void kernel_launch(void* const* d_in, const int* in_sizes, int n_in,
                              void* d_out, int out_size) {
    const int*   tokens = (const int*)d_in[0];
    const float* emb    = (const float*)d_in[1];
    const float* Wi     = (const float*)d_in[2];
    const float* Wh     = (const float*)d_in[3];
    const float* bh     = (const float*)d_in[4];
    const float* Wout   = (const float*)d_in[5];
    const float* bout   = (const float*)d_in[6];
    float* out = (float*)d_out;

    cudaFuncSetAttribute(gru_kernel, cudaFuncAttributeMaxDynamicSharedMemorySize, SMEM_DYN);

    reset_kernel<<<64, 256>>>();
    ew_kernel<<<dim3(24, 8), 256>>>(emb, Wi, bh);
    wprep_kernel<<<NBLK, 256>>>(Wh);
    woutprep_kernel<<<256, 256>>>(Wout);
    gru_kernel<<<NBLK + NOUT, 512, SMEM_DYN>>>(tokens, bh, bout, out);
}